// round 15
// baseline (speedup 1.0000x reference)
#include <cuda_runtime.h>
#include <cuda_fp16.h>
#include <stdint.h>

// Problem constants (fixed by the reference)
#define kBatch 32
#define kQ     16
#define kHq    32
#define kHkv   8
#define kG     4
#define kD     128
#define kPage  16
#define kPPS   256
#define kK     4096
#define kTile  32
#define kKStr  136            // K smem row stride (floats) — conflict-free score B-frag LDS.64
#define kVStr  132            // V smem row stride (floats) — conflict-free PV B-frag LDS.32
#define kStages 2
#define kSmemBytes (4*(kStages*kTile*(kKStr+kVStr)) + 4*64)  // 68864 B -> 3 CTAs/SM

// Split-KV: 4 chunks x 32 tiles; 1024 equal CTAs (measured-best schedule)
#define kSplit   4
#define kNTc     32                      // tiles per chunk
#define kItems   (kBatch*kHkv*kSplit)    // 1024

// Scratch: UNNORMALIZED partial O in fp16 + per-row (m, l) fp32 (log2 domain)
__device__ __half g_opart[(size_t)kSplit * 512 * 4096];       // 16 MB
__device__ float  g_ml[kSplit * kBatch * kHq * kQ * 2];       // 256 KB

__device__ __forceinline__ uint32_t packh2(float lo, float hi){
    __half2 h = __floats2half2_rn(lo, hi);
    return *reinterpret_cast<uint32_t*>(&h);
}
__device__ __forceinline__ float ex2f(float x){
    float y; asm("ex2.approx.ftz.f32 %0, %1;" : "=f"(y) : "f"(x)); return y;
}
__device__ __forceinline__ void mma16816(float* c, const uint32_t* a, uint32_t b0, uint32_t b1){
    asm volatile(
      "mma.sync.aligned.m16n8k16.row.col.f32.f16.f16.f32 "
      "{%0,%1,%2,%3}, {%4,%5,%6,%7}, {%8,%9}, {%0,%1,%2,%3};\n"
      : "+f"(c[0]), "+f"(c[1]), "+f"(c[2]), "+f"(c[3])
      : "r"(a[0]), "r"(a[1]), "r"(a[2]), "r"(a[3]), "r"(b0), "r"(b1));
}
__device__ __forceinline__ void cp16(uint32_t dst, const float* src){
    asm volatile("cp.async.cg.shared.global [%0], [%1], 16;\n" :: "r"(dst), "l"(src));
}

__global__ __launch_bounds__(128, 3)
void paged_gqa_part(const float* __restrict__ q,
                    const float* __restrict__ kc,
                    const float* __restrict__ vc,
                    const int*   __restrict__ pt)
{
    extern __shared__ float smem[];
    float* ksm = smem;
    float* vsm = smem + kStages*kTile*kKStr;
    int*   pts = (int*)(smem + kStages*kTile*(kKStr+kVStr));   // 64 page slots

    const int tid = threadIdx.x;
    const int w = tid >> 5, lane = tid & 31;
    const uint32_t ksm_s = (uint32_t)__cvta_generic_to_shared(ksm);
    const uint32_t vsm_s = (uint32_t)__cvta_generic_to_shared(vsm);
    const int ld_row0  = tid >> 5;        // 0..3
    const int ld_chunk = (tid & 31) * 4;  // float offset (16B per lane)
    const float scale = 1.4426950408889634f * rsqrtf((float)kD);

    const int item = blockIdx.x;
    const int s   = item >> 8;            // chunk 0..3
    const int rem = item & 255;
    const int b   = rem >> 3;
    const int h   = rem & 7;
    const int tile0 = kNTc * s;

    // ---- per-item page-table slice (2 pages per tile, 64 pages per chunk)
    if (tid < 64) pts[tid] = pt[b*kPPS + 64*s + tid];
    __syncthreads();

    // ---- Q fragments for this (b,h), warp = GQA lane g, pre-scaled
    uint32_t qf[8][4];
    {
        const int r0 = lane >> 2;
        const int c0 = (lane & 3) * 2;
        const float* q0 = q + (((size_t)(b*kQ + r0    ))*kHq + h*kG + w)*kD;
        const float* q1 = q + (((size_t)(b*kQ + r0 + 8))*kHq + h*kG + w)*kD;
        #pragma unroll
        for (int kk = 0; kk < 8; kk++){
            const int c = c0 + kk*16;
            float2 x0 = *(const float2*)(q0 + c);
            float2 x1 = *(const float2*)(q1 + c);
            float2 x2 = *(const float2*)(q0 + c + 8);
            float2 x3 = *(const float2*)(q1 + c + 8);
            qf[kk][0] = packh2(x0.x*scale, x0.y*scale);
            qf[kk][1] = packh2(x1.x*scale, x1.y*scale);
            qf[kk][2] = packh2(x2.x*scale, x2.y*scale);
            qf[kk][3] = packh2(x3.x*scale, x3.y*scale);
        }
    }

    float o[16][4];
    #pragma unroll
    for (int j = 0; j < 16; j++){ o[j][0]=o[j][1]=o[j][2]=o[j][3]=0.f; }
    float m0 = -1e30f, m1 = -1e30f, l0 = 0.f, l1 = 0.f;

    #define LOAD_TILE(t_) do {                                                        \
        const int st_ = (t_) & 1;                                                     \
        _Pragma("unroll")                                                             \
        for (int i_ = 0; i_ < 8; i_++){                                               \
            const int r_ = ld_row0 + i_*4;                                            \
            const int p_ = (t_)*kTile + r_;                                           \
            const int base_ = ((pts[p_ >> 4]*kPage + (p_ & 15))*kHkv + h)*kD + ld_chunk; \
            cp16(ksm_s + (uint32_t)(st_*kTile*kKStr + r_*kKStr + ld_chunk)*4, kc + base_); \
            cp16(vsm_s + (uint32_t)(st_*kTile*kVStr + r_*kVStr + ld_chunk)*4, vc + base_); \
        }                                                                             \
        asm volatile("cp.async.commit_group;\n");                                     \
    } while(0)

    LOAD_TILE(0);

    // Single barrier per tile: wait -> sync -> issue(t+1) -> compute(t).
    #pragma unroll 1
    for (int t = 0; t < kNTc; t++){
        asm volatile("cp.async.wait_group 0;\n");
        __syncthreads();
        if (t + 1 < kNTc) LOAD_TILE(t + 1);

        const float* ks = ksm + (t & 1)*kTile*kKStr;
        const float* vs = vsm + (t & 1)*kTile*kVStr;

        // ---- scores S[16 x 32] = Qw @ Ktile^T  (log2-scaled)
        float sc[4][4];
        #pragma unroll
        for (int j = 0; j < 4; j++) sc[j][0]=sc[j][1]=sc[j][2]=sc[j][3]=0.f;

        #pragma unroll
        for (int kk = 0; kk < 8; kk++){
            #pragma unroll
            for (int j = 0; j < 4; j++){
                const float* bp = ks + (8*j + (lane>>2))*kKStr + kk*16 + (lane&3)*2;
                float2 x = *(const float2*)bp;
                float2 y = *(const float2*)(bp + 8);
                mma16816(sc[j], qf[kk], packh2(x.x, x.y), packh2(y.x, y.y));
            }
        }

        // causal mask: only the globally-last tile (tile 127) is partial
        if (tile0 + t == 127){
            const int r0 = lane >> 2;
            #pragma unroll
            for (int j = 0; j < 4; j++){
                const int col = 8*j + (lane&3)*2;
                if (col     > 16 + r0) sc[j][0] = -1e30f;
                if (col + 1 > 16 + r0) sc[j][1] = -1e30f;
                if (col     > 24 + r0) sc[j][2] = -1e30f;
                if (col + 1 > 24 + r0) sc[j][3] = -1e30f;
            }
        }

        // ---- online softmax (base 2)
        float mx0 = fmaxf(fmaxf(sc[0][0],sc[0][1]), fmaxf(sc[1][0],sc[1][1]));
        mx0 = fmaxf(mx0, fmaxf(fmaxf(sc[2][0],sc[2][1]), fmaxf(sc[3][0],sc[3][1])));
        float mx1 = fmaxf(fmaxf(sc[0][2],sc[0][3]), fmaxf(sc[1][2],sc[1][3]));
        mx1 = fmaxf(mx1, fmaxf(fmaxf(sc[2][2],sc[2][3]), fmaxf(sc[3][2],sc[3][3])));
        mx0 = fmaxf(mx0, __shfl_xor_sync(0xffffffffu, mx0, 1));
        mx0 = fmaxf(mx0, __shfl_xor_sync(0xffffffffu, mx0, 2));
        mx1 = fmaxf(mx1, __shfl_xor_sync(0xffffffffu, mx1, 1));
        mx1 = fmaxf(mx1, __shfl_xor_sync(0xffffffffu, mx1, 2));
        const float nm0 = fmaxf(m0, mx0), nm1 = fmaxf(m1, mx1);
        const float a0 = ex2f(m0 - nm0), a1 = ex2f(m1 - nm1);
        m0 = nm0; m1 = nm1;
        l0 *= a0; l1 *= a1;
        #pragma unroll
        for (int j = 0; j < 4; j++){
            sc[j][0] = ex2f(sc[j][0] - m0);
            sc[j][1] = ex2f(sc[j][1] - m0);
            sc[j][2] = ex2f(sc[j][2] - m1);
            sc[j][3] = ex2f(sc[j][3] - m1);
            l0 += sc[j][0] + sc[j][1];
            l1 += sc[j][2] + sc[j][3];
        }
        if (__ballot_sync(0xffffffffu, (a0 != 1.f) || (a1 != 1.f))){
            #pragma unroll
            for (int j = 0; j < 16; j++){
                o[j][0]*=a0; o[j][1]*=a0; o[j][2]*=a1; o[j][3]*=a1;
            }
        }

        // ---- O += P @ Vtile  (P C-frags map exactly onto A-frags)
        #pragma unroll
        for (int k2 = 0; k2 < 2; k2++){
            uint32_t pa[4];
            pa[0] = packh2(sc[2*k2  ][0], sc[2*k2  ][1]);
            pa[1] = packh2(sc[2*k2  ][2], sc[2*k2  ][3]);
            pa[2] = packh2(sc[2*k2+1][0], sc[2*k2+1][1]);
            pa[3] = packh2(sc[2*k2+1][2], sc[2*k2+1][3]);
            const float* vb = vs + (k2*16 + (lane&3)*2)*kVStr + (lane>>2);
            #pragma unroll
            for (int jd = 0; jd < 16; jd++){
                const float* p0 = vb + jd*8;
                uint32_t b0 = packh2(p0[0],        p0[kVStr]);
                uint32_t b1 = packh2(p0[8*kVStr],  p0[9*kVStr]);
                mma16816(o[jd], pa, b0, b1);
            }
        }
    }
    #undef LOAD_TILE

    // ---- epilogue: quad-reduce l, store UNNORMALIZED partial O (fp16) + (m,l)
    l0 += __shfl_xor_sync(0xffffffffu, l0, 1);
    l0 += __shfl_xor_sync(0xffffffffu, l0, 2);
    l1 += __shfl_xor_sync(0xffffffffu, l1, 1);
    l1 += __shfl_xor_sync(0xffffffffu, l1, 2);

    const int r0 = lane >> 2;
    const int hq = h*kG + w;
    __half* o0 = g_opart + (((size_t)(s*512 + b*kQ + r0    ))*4096) + hq*kD + (lane&3)*2;
    __half* o1 = g_opart + (((size_t)(s*512 + b*kQ + r0 + 8))*4096) + hq*kD + (lane&3)*2;
    #pragma unroll
    for (int jd = 0; jd < 16; jd++){
        *(uint32_t*)(o0 + jd*8) = packh2(o[jd][0], o[jd][1]);
        *(uint32_t*)(o1 + jd*8) = packh2(o[jd][2], o[jd][3]);
    }
    if ((lane & 3) == 0){
        const int i0 = ((((s*kBatch + b)*kHq + hq)*kQ) + r0)*2;
        g_ml[i0]      = m0; g_ml[i0 + 1]  = l0;
        g_ml[i0 + 16] = m1; g_ml[i0 + 17] = l1;   // rows r0+8
    }
}

// merge kSplit partial results: out = sum_s 2^(m_s-m*) O_s / sum_s 2^(m_s-m*) l_s
// Widened: each thread produces 8 consecutive floats — one 16B partial load per
// split (4 independent LDG.128) instead of 2x8B per 4 floats. m/l loads are
// warp-uniform per 16-thread group (same hq) -> broadcast.
__global__ __launch_bounds__(256)
void paged_gqa_combine(float* __restrict__ out)
{
    const int idx = blockIdx.x * 256 + threadIdx.x;     // [0, 512*512)
    const int row = idx >> 9;             // b*16 + q
    const int c8  = idx & 511;            // 8-float column group
    const int b   = row >> 4;
    const int qi  = row & 15;
    const int hq  = c8 >> 4;              // (c8*8) / 128

    float m[kSplit], l[kSplit];
    float mstar = -1e30f;
    #pragma unroll
    for (int s = 0; s < kSplit; s++){
        const int i0 = ((((s*kBatch + b)*kHq + hq)*kQ) + qi)*2;
        m[s] = g_ml[i0]; l[s] = g_ml[i0 + 1];
        mstar = fmaxf(mstar, m[s]);
    }

    // batch the 4 independent 16B partial loads up front (MLP=4)
    uint4 raw[kSplit];
    #pragma unroll
    for (int s = 0; s < kSplit; s++){
        raw[s] = *(const uint4*)(g_opart + ((size_t)(s*512 + row))*4096 + c8*8);
    }

    float denom = 0.f;
    float acc[8] = {0.f,0.f,0.f,0.f,0.f,0.f,0.f,0.f};
    #pragma unroll
    for (int s = 0; s < kSplit; s++){
        const float wgt = ex2f(m[s] - mstar);
        denom += wgt * l[s];
        const uint32_t* rp = &raw[s].x;
        #pragma unroll
        for (int i = 0; i < 4; i++){
            float2 v = __half22float2(*reinterpret_cast<const __half2*>(&rp[i]));
            acc[2*i]   += wgt * v.x;
            acc[2*i+1] += wgt * v.y;
        }
    }
    const float inv = 1.0f / denom;
    float4 r0 = make_float4(acc[0]*inv, acc[1]*inv, acc[2]*inv, acc[3]*inv);
    float4 r1 = make_float4(acc[4]*inv, acc[5]*inv, acc[6]*inv, acc[7]*inv);
    float* op = out + (size_t)idx * 8;
    *(float4*)(op)     = r0;
    *(float4*)(op + 4) = r1;
}

extern "C" void kernel_launch(void* const* d_in, const int* in_sizes, int n_in,
                              void* d_out, int out_size)
{
    const float* q  = (const float*)d_in[0];   // [32,16,32,128] f32
    const float* kc = (const float*)d_in[1];   // [8192,16,8,128] f32
    const float* vc = (const float*)d_in[2];   // [8192,16,8,128] f32
    const int*   pt = (const int*)  d_in[3];   // [32,256] i32
    float* out = (float*)d_out;                // [512,4096] f32

    cudaFuncSetAttribute(paged_gqa_part,
                         cudaFuncAttributeMaxDynamicSharedMemorySize, kSmemBytes);
    paged_gqa_part<<<kItems, 128, kSmemBytes>>>(q, kc, vc, pt);
    paged_gqa_combine<<<(512*512)/256, 256>>>(out);
}